// round 1
// baseline (speedup 1.0000x reference)
#include <cuda_runtime.h>

#define NB 8
#define CIN 64
#define PP 2304            // 48*48 positions
#define OUTC 384
#define NSTRIDE (OUTC*PP)  // per-batch stride in d_out
#define SLICE (64*PP)      // per-stage channel-slice stride

// Scratch (allocation-free rule: __device__ globals)
__device__ float g_q[NB*8*PP];
__device__ float g_k[NB*8*PP];
__device__ float g_v[NB*32*PP];

typedef unsigned long long u64;

__device__ __forceinline__ u64 fma2(u64 a, u64 b, u64 c) {
    u64 d; asm("fma.rn.f32x2 %0, %1, %2, %3;" : "=l"(d) : "l"(a), "l"(b), "l"(c)); return d;
}
__device__ __forceinline__ u64 add2(u64 a, u64 b) {
    u64 d; asm("add.rn.f32x2 %0, %1, %2;" : "=l"(d) : "l"(a), "l"(b)); return d;
}
__device__ __forceinline__ u64 pack2(float lo, float hi) {
    u64 d; asm("mov.b64 %0, {%1, %2};" : "=l"(d) : "f"(lo), "f"(hi)); return d;
}
__device__ __forceinline__ void unpack2(u64 v, float& lo, float& hi) {
    asm("mov.b64 {%0, %1}, %2;" : "=f"(lo), "=f"(hi) : "l"(v));
}

// ---------------------------------------------------------------------------
// Fused QKV 1x1 conv: 64 in -> 8 (q) + 8 (k) + 32 (v, ReLU).
// src points at the 64-channel slice start; bstride = elements between batches.
// ---------------------------------------------------------------------------
__global__ void qkv_kernel(const float* __restrict__ src, long bstride,
                           const float* __restrict__ qw, const float* __restrict__ qb,
                           const float* __restrict__ kw, const float* __restrict__ kb,
                           const float* __restrict__ vw, const float* __restrict__ vb)
{
    __shared__ float wt[CIN*48];   // [c][o], broadcast-friendly
    __shared__ float bs[48];
    const int tid = threadIdx.x;

    for (int i = tid; i < 48*CIN; i += blockDim.x) {
        int o = i % 48, c = i / 48;
        float v;
        if (o < 8)       v = qw[o*CIN + c];
        else if (o < 16) v = kw[(o-8)*CIN + c];
        else             v = vw[(o-16)*CIN + c];
        wt[c*48 + o] = v;
    }
    if (tid < 48)
        bs[tid] = (tid < 8) ? qb[tid] : (tid < 16 ? kb[tid-8] : vb[tid-16]);
    __syncthreads();

    const int gid = blockIdx.x * blockDim.x + tid;
    const int n = gid / PP, p = gid % PP;
    const float* xb = src + (long)n * bstride + p;

    float acc[48];
    #pragma unroll
    for (int o = 0; o < 48; o++) acc[o] = 0.f;

    for (int c = 0; c < CIN; c++) {
        float xv = xb[(long)c * PP];
        const float4* w4 = (const float4*)(wt + c*48);
        #pragma unroll
        for (int t = 0; t < 12; t++) {
            float4 w = w4[t];
            acc[4*t+0] += w.x * xv;
            acc[4*t+1] += w.y * xv;
            acc[4*t+2] += w.z * xv;
            acc[4*t+3] += w.w * xv;
        }
    }

    #pragma unroll
    for (int o = 0; o < 8; o++)  g_q[(n*8  + o)*PP + p] = acc[o]      + bs[o];
    #pragma unroll
    for (int o = 0; o < 8; o++)  g_k[(n*8  + o)*PP + p] = acc[8+o]    + bs[8+o];
    #pragma unroll
    for (int o = 0; o < 32; o++) g_v[(n*32 + o)*PP + p] = fmaxf(acc[16+o] + bs[16+o], 0.f);
}

// ---------------------------------------------------------------------------
// Visual attention (2304x2304, d=8, dv=32) + out-conv(32->32) + concat write.
// Grid: 8 batches x 18 query tiles of 128. 128 threads, 1 query each.
// One-pass softmax (logits are O(1) with these weight scales; shift-invariant).
// ---------------------------------------------------------------------------
__global__ void vis_attn_kernel(const float* __restrict__ cw, const float* __restrict__ cb,
                                float* __restrict__ out)
{
    __shared__ float ks[128*8];    // [j][c]
    __shared__ float vs[128*40];   // [j][c] padded row=40 (16B aligned, reduced conflicts)
    __shared__ float cwt[32*32];   // [c][o]
    __shared__ float cbs[32];

    const int tid = threadIdx.x;
    const int n = blockIdx.x / 18;
    const int qpos = (blockIdx.x % 18) * 128 + tid;

    for (int i = tid; i < 32*32; i += 128)
        cwt[(i % 32)*32 + (i / 32)] = cw[i];
    if (tid < 32) cbs[tid] = cb[tid];

    const float* qb_ = g_q + n*8*PP;
    const float* kb_ = g_k + n*8*PP;
    const float* vb_ = g_v + n*32*PP;

    float qv[8];
    #pragma unroll
    for (int c = 0; c < 8; c++) qv[c] = qb_[c*PP + qpos];
    const u64 q01 = pack2(qv[0], qv[1]);
    const u64 q23 = pack2(qv[2], qv[3]);
    const u64 q45 = pack2(qv[4], qv[5]);
    const u64 q67 = pack2(qv[6], qv[7]);

    u64 vacc[16];
    #pragma unroll
    for (int t = 0; t < 16; t++) vacc[t] = 0ULL;
    float l = 0.f;

    for (int ch = 0; ch < 18; ch++) {
        __syncthreads();
        const int base = ch*128 + tid;
        #pragma unroll
        for (int r = 0; r < 8; r++)  ks[tid*8  + r] = kb_[r*PP + base];
        #pragma unroll
        for (int r = 0; r < 32; r++) vs[tid*40 + r] = vb_[r*PP + base];
        __syncthreads();

        #pragma unroll 4
        for (int j = 0; j < 128; j++) {
            const u64* kr = (const u64*)(ks + j*8);
            u64 d0 = fma2(q01, kr[0], fma2(q23, kr[1], 0ULL));
            u64 d1 = fma2(q45, kr[2], fma2(q67, kr[3], 0ULL));
            u64 ds = add2(d0, d1);
            float lo, hi; unpack2(ds, lo, hi);
            float p = __expf(lo + hi);
            l += p;
            u64 p2 = pack2(p, p);
            const u64* vr = (const u64*)(vs + j*40);
            #pragma unroll
            for (int t = 0; t < 16; t++) vacc[t] = fma2(p2, vr[t], vacc[t]);
        }
    }

    // normalize
    float a[32];
    const float inv = 1.f / l;
    #pragma unroll
    for (int t = 0; t < 16; t++) {
        float lo, hi; unpack2(vacc[t], lo, hi);
        a[2*t]   = lo * inv;
        a[2*t+1] = hi * inv;
    }

    // out-conv 32->32
    float oc[32];
    #pragma unroll
    for (int o = 0; o < 32; o++) oc[o] = cbs[o];
    #pragma unroll
    for (int c = 0; c < 32; c++) {
        float av = a[c];
        const float4* w4 = (const float4*)(cwt + c*32);
        #pragma unroll
        for (int t = 0; t < 8; t++) {
            float4 w = w4[t];
            oc[4*t+0] += w.x * av;
            oc[4*t+1] += w.y * av;
            oc[4*t+2] += w.z * av;
            oc[4*t+3] += w.w * av;
        }
    }

    float* ob = out + (long)n * NSTRIDE + qpos;
    #pragma unroll
    for (int o = 0; o < 32; o++) ob[o*PP] = oc[o];
    #pragma unroll
    for (int c = 0; c < 32; c++) ob[(32+c)*PP] = vb_[c*PP + qpos];
}

// ---------------------------------------------------------------------------
// Temporal attention over frames [n-2, n-1, n] (zero-padded) + out-conv + concat.
// outslice points at d_out + (stage+1)*SLICE.
// ---------------------------------------------------------------------------
__global__ void temporal_kernel(const float* __restrict__ cw, const float* __restrict__ cb,
                                float* __restrict__ outslice)
{
    __shared__ float cwt[32*32];
    __shared__ float cbs[32];
    const int tid = threadIdx.x;
    for (int i = tid; i < 32*32; i += blockDim.x)
        cwt[(i % 32)*32 + (i / 32)] = cw[i];
    if (tid < 32) cbs[tid] = cb[tid];
    __syncthreads();

    const int gid = blockIdx.x * blockDim.x + tid;
    const int n = gid / PP, p = gid % PP;

    float qv[8];
    #pragma unroll
    for (int c = 0; c < 8; c++) qv[c] = g_q[(n*8 + c)*PP + p];

    float l2 = 0.f, l1 = 0.f, l0 = 0.f;
    #pragma unroll
    for (int c = 0; c < 8; c++) l2 += g_k[(n*8 + c)*PP + p] * qv[c];
    if (n >= 1) {
        #pragma unroll
        for (int c = 0; c < 8; c++) l1 += g_k[((n-1)*8 + c)*PP + p] * qv[c];
    }
    if (n >= 2) {
        #pragma unroll
        for (int c = 0; c < 8; c++) l0 += g_k[((n-2)*8 + c)*PP + p] * qv[c];
    }
    // zero-padded frames contribute logit exactly 0 (dot with zero tensor), and
    // they DO participate in the softmax — matches reference precede() semantics.
    float m = fmaxf(l0, fmaxf(l1, l2));
    float e0 = __expf(l0 - m), e1 = __expf(l1 - m), e2 = __expf(l2 - m);
    float inv = 1.f / (e0 + e1 + e2);
    float a0 = e0*inv, a1 = e1*inv, a2 = e2*inv;

    float vv[32];
    #pragma unroll
    for (int c = 0; c < 32; c++) {
        float s = a2 * g_v[(n*32 + c)*PP + p];
        if (n >= 1) s += a1 * g_v[((n-1)*32 + c)*PP + p];
        if (n >= 2) s += a0 * g_v[((n-2)*32 + c)*PP + p];
        vv[c] = s;
    }

    float oc[32];
    #pragma unroll
    for (int o = 0; o < 32; o++) oc[o] = cbs[o];
    #pragma unroll
    for (int c = 0; c < 32; c++) {
        float av = vv[c];
        const float4* w4 = (const float4*)(cwt + c*32);
        #pragma unroll
        for (int t = 0; t < 8; t++) {
            float4 w = w4[t];
            oc[4*t+0] += w.x * av;
            oc[4*t+1] += w.y * av;
            oc[4*t+2] += w.z * av;
            oc[4*t+3] += w.w * av;
        }
    }

    float* ob = outslice + (long)n * NSTRIDE + p;
    #pragma unroll
    for (int o = 0; o < 32; o++) ob[o*PP] = oc[o];
    #pragma unroll
    for (int c = 0; c < 32; c++) ob[(32+c)*PP] = g_v[(n*32 + c)*PP + p];
}

// ---------------------------------------------------------------------------
extern "C" void kernel_launch(void* const* d_in, const int* in_sizes, int n_in,
                              void* d_out, int out_size)
{
    const float* x    = (const float*)d_in[0];
    const float* vq_w = (const float*)d_in[1];
    const float* vq_b = (const float*)d_in[2];
    const float* vk_w = (const float*)d_in[3];
    const float* vk_b = (const float*)d_in[4];
    const float* vv_w = (const float*)d_in[5];
    const float* vv_b = (const float*)d_in[6];
    const float* vc_w = (const float*)d_in[7];
    const float* vc_b = (const float*)d_in[8];
    const float* tq_w = (const float*)d_in[9];
    const float* tq_b = (const float*)d_in[10];
    const float* tk_w = (const float*)d_in[11];
    const float* tk_b = (const float*)d_in[12];
    const float* tv_w = (const float*)d_in[13];
    const float* tv_b = (const float*)d_in[14];
    const float* tc_w = (const float*)d_in[15];
    const float* tc_b = (const float*)d_in[16];
    float* out = (float*)d_out;

    const int nblk = (NB * PP) / 128;  // 144

    // Visual head -> slice 0
    qkv_kernel<<<nblk, 128>>>(x, (long)CIN*PP, vq_w, vq_b, vk_w, vk_b, vv_w, vv_b);
    vis_attn_kernel<<<nblk, 128>>>(vc_w, vc_b, out);

    // 5 temporal heads: read slice i, write slice i+1
    for (int i = 0; i < 5; i++) {
        qkv_kernel<<<nblk, 128>>>(out + (long)i*SLICE, (long)NSTRIDE,
                                  tq_w + i*8*CIN,  tq_b + i*8,
                                  tk_w + i*8*CIN,  tk_b + i*8,
                                  tv_w + i*32*CIN, tv_b + i*32);
        temporal_kernel<<<nblk, 128>>>(tc_w + i*32*32, tc_b + i*32,
                                       out + (long)(i+1)*SLICE);
    }
}

// round 2
// speedup vs baseline: 1.7561x; 1.7561x over previous
#include <cuda_runtime.h>

#define NB 8
#define PP 2304
#define QTOT (NB*PP)       // 18432
#define CIN 64
#define OUTC 384
#define NSTRIDE (OUTC*PP)
#define SLICE (64*PP)
#define NS 9               // split-K factor (18 key-chunks / 2 per split)

// Scratch (allocation-free rule: __device__ globals). Double-buffered q/k/v.
__device__ float g_q[2][NB*8*PP];
__device__ float g_k[2][NB*8*PP];
__device__ float g_v[2][NB*32*PP];
__device__ float g_pl[NS*QTOT];
__device__ float g_pv[NS*32*QTOT];

typedef unsigned long long u64;

__device__ __forceinline__ u64 fma2(u64 a,u64 b,u64 c){u64 d;asm("fma.rn.f32x2 %0,%1,%2,%3;":"=l"(d):"l"(a),"l"(b),"l"(c));return d;}
__device__ __forceinline__ u64 add2(u64 a,u64 b){u64 d;asm("add.rn.f32x2 %0,%1,%2;":"=l"(d):"l"(a),"l"(b));return d;}
__device__ __forceinline__ u64 pack2(float lo,float hi){u64 d;asm("mov.b64 %0,{%1,%2};":"=l"(d):"f"(lo),"f"(hi));return d;}
__device__ __forceinline__ void unpack2(u64 v,float&lo,float&hi){asm("mov.b64 {%0,%1},%2;":"=f"(lo),"=f"(hi):"l"(v));}

// ---------------------------------------------------------------------------
// Stage-0 QKV: 64 -> 8(q) + 8(k) + 32(v,ReLU), packed f32x2 math.
// ---------------------------------------------------------------------------
__global__ __launch_bounds__(128) void qkv_kernel(
    const float* __restrict__ src,
    const float* __restrict__ qw, const float* __restrict__ qb,
    const float* __restrict__ kw, const float* __restrict__ kb,
    const float* __restrict__ vw, const float* __restrict__ vb)
{
    __shared__ alignas(16) u64 swt[CIN*24];   // [c][o2] packed output pairs
    __shared__ float sbs[48];
    const int tid = threadIdx.x;
    for (int i = tid; i < CIN*24; i += 128) {
        int c = i / 24, o2 = (i % 24) * 2, o1 = o2 + 1;
        float w0 = (o2 < 8) ? qw[o2*CIN+c] : (o2 < 16 ? kw[(o2-8)*CIN+c] : vw[(o2-16)*CIN+c]);
        float w1 = (o1 < 8) ? qw[o1*CIN+c] : (o1 < 16 ? kw[(o1-8)*CIN+c] : vw[(o1-16)*CIN+c]);
        swt[i] = pack2(w0, w1);
    }
    if (tid < 48) sbs[tid] = (tid<8)?qb[tid]:(tid<16?kb[tid-8]:vb[tid-16]);
    __syncthreads();

    const int gid = blockIdx.x*128 + tid;
    const int n = gid / PP, p = gid % PP;
    u64 acc[24];
    #pragma unroll
    for (int t=0;t<24;t++) acc[t] = pack2(sbs[2*t], sbs[2*t+1]);
    const float* xb = src + (long)n*CIN*PP + p;
    for (int c=0;c<CIN;c++) {
        float xv = xb[c*PP];
        u64 x2 = pack2(xv,xv);
        const ulonglong2* w2 = (const ulonglong2*)(swt + c*24);
        #pragma unroll
        for (int t=0;t<12;t++) { ulonglong2 w = w2[t];
            acc[2*t]   = fma2(x2, w.x, acc[2*t]);
            acc[2*t+1] = fma2(x2, w.y, acc[2*t+1]); }
    }
    float o[48];
    #pragma unroll
    for (int t=0;t<24;t++) unpack2(acc[t], o[2*t], o[2*t+1]);
    #pragma unroll
    for (int i=0;i<8;i++)  g_q[0][(n*8+i)*PP+p] = o[i];
    #pragma unroll
    for (int i=0;i<8;i++)  g_k[0][(n*8+i)*PP+p] = o[8+i];
    #pragma unroll
    for (int i=0;i<32;i++) g_v[0][(n*32+i)*PP+p] = fmaxf(o[16+i], 0.f);
}

// ---------------------------------------------------------------------------
// Visual attention, split-K: 48 query-tiles (384 q each, 3 q/thread) x 9 splits.
// One-pass softmax (no max subtraction; logits O(1)); partials to g_pl/g_pv.
// ---------------------------------------------------------------------------
__global__ __launch_bounds__(128) void vis_attn_split(void)
{
    __shared__ alignas(16) u64 ksu[4*128];    // [c2][j]
    __shared__ alignas(16) u64 vsu[16*128];   // [c2][j]
    const int tid = threadIdx.x;
    const int tile = blockIdx.x / NS, split = blockIdx.x % NS;
    const int n = tile / 6, tw = tile % 6;
    const int qp = tw*384 + tid;
    const float* qb_ = g_q[0] + n*8*PP;
    const float* kb_ = g_k[0] + n*8*PP;
    const float* vb_ = g_v[0] + n*32*PP;

    u64 qr[3][4];
    #pragma unroll
    for (int i=0;i<3;i++)
        #pragma unroll
        for (int r=0;r<4;r++)
            qr[i][r] = pack2(qb_[(2*r)*PP + qp + i*128], qb_[(2*r+1)*PP + qp + i*128]);

    float l[3] = {0.f, 0.f, 0.f};
    u64 vacc[3][16];
    #pragma unroll
    for (int i=0;i<3;i++)
        #pragma unroll
        for (int t=0;t<16;t++) vacc[i][t] = 0ULL;

    const u64 z = 0ULL;
    for (int ch = split*2; ch < split*2 + 2; ch++) {
        __syncthreads();
        const int base = ch*128 + tid;
        #pragma unroll
        for (int r=0;r<4;r++)  ksu[r*128+tid] = pack2(kb_[(2*r)*PP+base], kb_[(2*r+1)*PP+base]);
        #pragma unroll
        for (int t=0;t<16;t++) vsu[t*128+tid] = pack2(vb_[(2*t)*PP+base], vb_[(2*t+1)*PP+base]);
        __syncthreads();
        #pragma unroll 2
        for (int j=0;j<128;j++) {
            u64 k0 = ksu[j], k1 = ksu[128+j], k2 = ksu[256+j], k3 = ksu[384+j];
            float pr[3];
            #pragma unroll
            for (int i=0;i<3;i++) {
                u64 d = add2(fma2(qr[i][0],k0,fma2(qr[i][1],k1,z)),
                             fma2(qr[i][2],k2,fma2(qr[i][3],k3,z)));
                float lo,hi; unpack2(d,lo,hi);
                pr[i] = __expf(lo + hi);
                l[i] += pr[i];
            }
            u64 p0 = pack2(pr[0],pr[0]), p1 = pack2(pr[1],pr[1]), p2 = pack2(pr[2],pr[2]);
            #pragma unroll
            for (int t=0;t<16;t++) {
                u64 vr = vsu[t*128+j];
                vacc[0][t] = fma2(p0, vr, vacc[0][t]);
                vacc[1][t] = fma2(p1, vr, vacc[1][t]);
                vacc[2][t] = fma2(p2, vr, vacc[2][t]);
            }
        }
    }
    #pragma unroll
    for (int i=0;i<3;i++) {
        int q = n*PP + qp + i*128;
        g_pl[split*QTOT + q] = l[i];
        #pragma unroll
        for (int t=0;t<16;t++) {
            float lo,hi; unpack2(vacc[i][t], lo, hi);
            g_pv[(split*32 + 2*t  )*QTOT + q] = lo;
            g_pv[(split*32 + 2*t+1)*QTOT + q] = hi;
        }
    }
}

// ---------------------------------------------------------------------------
// Shared epilogue: out-conv(32->32) + concat write + (optional) next-stage QKV.
// Register arrays made dynamically indexable via conflict-free xs staging.
// ---------------------------------------------------------------------------
struct alignas(16) TailSmem {
    u64  cwt[32*16];     // conv weights [c][o2]
    float cbs[32];
    u64  swt[CIN*24];    // next-stage qkv weights [c][o2]
    float sbs[48];
    float xs[32*128];    // staging: [c][tid]
};

__device__ __forceinline__ void fill_tail_smem(TailSmem* s, int tid,
    const float* cw, const float* cb,
    const float* qw, const float* qb, const float* kw, const float* kb,
    const float* vw, const float* vb, int has_next)
{
    for (int i = tid; i < 32*16; i += 128) {
        int c = i/16, t = i%16;
        s->cwt[i] = pack2(cw[(2*t)*32+c], cw[(2*t+1)*32+c]);
    }
    if (tid < 32) s->cbs[tid] = cb[tid];
    if (has_next) {
        for (int i = tid; i < CIN*24; i += 128) {
            int c = i/24, o2 = (i%24)*2, o1 = o2+1;
            float w0 = (o2<8)?qw[o2*CIN+c]:(o2<16?kw[(o2-8)*CIN+c]:vw[(o2-16)*CIN+c]);
            float w1 = (o1<8)?qw[o1*CIN+c]:(o1<16?kw[(o1-8)*CIN+c]:vw[(o1-16)*CIN+c]);
            s->swt[i] = pack2(w0,w1);
        }
        if (tid < 48) s->sbs[tid] = (tid<8)?qb[tid]:(tid<16?kb[tid-8]:vb[tid-16]);
    }
}

__device__ __forceinline__ void tail_conv_concat_qkv(
    TailSmem* s, const float* a, const float* vv,
    int n, int p, float* ob, int tid, int has_next, int dst)
{
    // conv 32->32 over a[]
    __syncthreads();
    #pragma unroll
    for (int c=0;c<32;c++) s->xs[c*128+tid] = a[c];
    u64 acc[16];
    #pragma unroll
    for (int t=0;t<16;t++) acc[t] = pack2(s->cbs[2*t], s->cbs[2*t+1]);
    __syncthreads();
    for (int c=0;c<32;c++) {
        float xv = s->xs[c*128+tid]; u64 x2 = pack2(xv,xv);
        const ulonglong2* w2 = (const ulonglong2*)(s->cwt + c*16);
        #pragma unroll
        for (int t=0;t<8;t++){ ulonglong2 w = w2[t];
            acc[2*t] = fma2(x2,w.x,acc[2*t]); acc[2*t+1] = fma2(x2,w.y,acc[2*t+1]); }
    }
    float oc[32];
    #pragma unroll
    for (int t=0;t<16;t++) unpack2(acc[t], oc[2*t], oc[2*t+1]);
    #pragma unroll
    for (int o=0;o<32;o++) ob[o*PP] = oc[o];
    #pragma unroll
    for (int c=0;c<32;c++) ob[(32+c)*PP] = vv[c];
    if (!has_next) return;

    // next-stage qkv over x64 = [oc, vv]
    u64 acc2[24];
    #pragma unroll
    for (int t=0;t<24;t++) acc2[t] = pack2(s->sbs[2*t], s->sbs[2*t+1]);
    __syncthreads();
    #pragma unroll
    for (int c=0;c<32;c++) s->xs[c*128+tid] = oc[c];
    __syncthreads();
    for (int c=0;c<32;c++) {
        float xv = s->xs[c*128+tid]; u64 x2 = pack2(xv,xv);
        const ulonglong2* w2 = (const ulonglong2*)(s->swt + c*24);
        #pragma unroll
        for (int t=0;t<12;t++){ ulonglong2 w = w2[t];
            acc2[2*t] = fma2(x2,w.x,acc2[2*t]); acc2[2*t+1] = fma2(x2,w.y,acc2[2*t+1]); }
    }
    __syncthreads();
    #pragma unroll
    for (int c=0;c<32;c++) s->xs[c*128+tid] = vv[c];
    __syncthreads();
    for (int c=0;c<32;c++) {
        float xv = s->xs[c*128+tid]; u64 x2 = pack2(xv,xv);
        const ulonglong2* w2 = (const ulonglong2*)(s->swt + (32+c)*24);
        #pragma unroll
        for (int t=0;t<12;t++){ ulonglong2 w = w2[t];
            acc2[2*t] = fma2(x2,w.x,acc2[2*t]); acc2[2*t+1] = fma2(x2,w.y,acc2[2*t+1]); }
    }
    float o[48];
    #pragma unroll
    for (int t=0;t<24;t++) unpack2(acc2[t], o[2*t], o[2*t+1]);
    #pragma unroll
    for (int i=0;i<8;i++)  g_q[dst][(n*8+i)*PP+p] = o[i];
    #pragma unroll
    for (int i=0;i<8;i++)  g_k[dst][(n*8+i)*PP+p] = o[8+i];
    #pragma unroll
    for (int i=0;i<32;i++) g_v[dst][(n*32+i)*PP+p] = fmaxf(o[16+i], 0.f);
}

// ---------------------------------------------------------------------------
// Combine split-K partials + out-conv + concat + stage-1 QKV (-> buf 1).
// ---------------------------------------------------------------------------
__global__ __launch_bounds__(128) void combine_kernel(
    const float* __restrict__ cw, const float* __restrict__ cb,
    const float* __restrict__ qw, const float* __restrict__ qb,
    const float* __restrict__ kw, const float* __restrict__ kb,
    const float* __restrict__ vw, const float* __restrict__ vb,
    float* __restrict__ out)
{
    __shared__ TailSmem s;
    const int tid = threadIdx.x;
    fill_tail_smem(&s, tid, cw, cb, qw, qb, kw, kb, vw, vb, 1);
    const int gid = blockIdx.x*128 + tid;
    const int n = gid/PP, p = gid%PP;

    float l = 0.f;
    #pragma unroll
    for (int sp=0; sp<NS; sp++) l += g_pl[sp*QTOT + gid];
    float va[32];
    #pragma unroll
    for (int c=0;c<32;c++) va[c] = 0.f;
    for (int sp=0; sp<NS; sp++) {
        #pragma unroll
        for (int c=0;c<32;c++) va[c] += g_pv[(sp*32+c)*QTOT + gid];
    }
    float inv = 1.f / l;
    #pragma unroll
    for (int c=0;c<32;c++) va[c] *= inv;
    float vv[32];
    #pragma unroll
    for (int c=0;c<32;c++) vv[c] = g_v[0][(n*32+c)*PP+p];

    float* ob = out + (long)n*NSTRIDE + p;   // slice 0
    tail_conv_concat_qkv(&s, va, vv, n, p, ob, tid, 1, 1);
}

// ---------------------------------------------------------------------------
// Temporal head h: 3-frame softmax attention + epilogue (+ next-stage QKV).
// ---------------------------------------------------------------------------
__global__ __launch_bounds__(128) void temporal_kernel(
    int src, int dst, int has_next,
    const float* __restrict__ cw, const float* __restrict__ cb,
    const float* __restrict__ qw, const float* __restrict__ qb,
    const float* __restrict__ kw, const float* __restrict__ kb,
    const float* __restrict__ vw, const float* __restrict__ vb,
    float* __restrict__ outslice)
{
    __shared__ TailSmem s;
    const int tid = threadIdx.x;
    fill_tail_smem(&s, tid, cw, cb, qw, qb, kw, kb, vw, vb, has_next);
    const int gid = blockIdx.x*128 + tid;
    const int n = gid/PP, p = gid%PP;
    const float* Q = g_q[src];
    const float* K = g_k[src];
    const float* V = g_v[src];

    float qv[8];
    #pragma unroll
    for (int c=0;c<8;c++) qv[c] = Q[(n*8+c)*PP+p];
    float l2=0.f, l1=0.f, l0=0.f;
    #pragma unroll
    for (int c=0;c<8;c++) l2 += K[(n*8+c)*PP+p]*qv[c];
    if (n >= 1) {
        #pragma unroll
        for (int c=0;c<8;c++) l1 += K[((n-1)*8+c)*PP+p]*qv[c];
    }
    if (n >= 2) {
        #pragma unroll
        for (int c=0;c<8;c++) l0 += K[((n-2)*8+c)*PP+p]*qv[c];
    }
    // zero-padded frames have logit exactly 0 and participate in the softmax
    float m  = fmaxf(l0, fmaxf(l1, l2));
    float e0 = __expf(l0-m), e1 = __expf(l1-m), e2 = __expf(l2-m);
    float inv = 1.f/(e0+e1+e2);
    float a0 = e0*inv, a1 = e1*inv, a2 = e2*inv;

    float vc[32], av[32];
    #pragma unroll
    for (int c=0;c<32;c++) {
        vc[c] = V[(n*32+c)*PP+p];
        float sacc = a2*vc[c];
        if (n >= 1) sacc += a1*V[((n-1)*32+c)*PP+p];
        if (n >= 2) sacc += a0*V[((n-2)*32+c)*PP+p];
        av[c] = sacc;
    }
    float* ob = outslice + (long)n*NSTRIDE + p;
    tail_conv_concat_qkv(&s, av, vc, n, p, ob, tid, has_next, dst);
}

// ---------------------------------------------------------------------------
extern "C" void kernel_launch(void* const* d_in, const int* in_sizes, int n_in,
                              void* d_out, int out_size)
{
    const float* x    = (const float*)d_in[0];
    const float* vq_w = (const float*)d_in[1];
    const float* vq_b = (const float*)d_in[2];
    const float* vk_w = (const float*)d_in[3];
    const float* vk_b = (const float*)d_in[4];
    const float* vv_w = (const float*)d_in[5];
    const float* vv_b = (const float*)d_in[6];
    const float* vc_w = (const float*)d_in[7];
    const float* vc_b = (const float*)d_in[8];
    const float* tq_w = (const float*)d_in[9];
    const float* tq_b = (const float*)d_in[10];
    const float* tk_w = (const float*)d_in[11];
    const float* tk_b = (const float*)d_in[12];
    const float* tv_w = (const float*)d_in[13];
    const float* tv_b = (const float*)d_in[14];
    const float* tc_w = (const float*)d_in[15];
    const float* tc_b = (const float*)d_in[16];
    float* out = (float*)d_out;

    qkv_kernel<<<144,128>>>(x, vq_w, vq_b, vk_w, vk_b, vv_w, vv_b);   // -> buf 0
    vis_attn_split<<<48*NS,128>>>();                                   // partials
    combine_kernel<<<144,128>>>(vc_w, vc_b,
                                tq_w, tq_b, tk_w, tk_b, tv_w, tv_b,    // head-0 qkv
                                out);                                  // slice 0, -> buf 1

    for (int h = 0; h < 5; h++) {
        int hn = (h < 4);
        int nh = hn ? h+1 : 0;   // next head weight index (unused when hn=0)
        temporal_kernel<<<144,128>>>((h+1)&1, h&1, hn,
            tc_w + h*1024, tc_b + h*32,
            tq_w + nh*512,  tq_b + nh*8,
            tk_w + nh*512,  tk_b + nh*8,
            tv_w + nh*2048, tv_b + nh*32,
            out + (long)(h+1)*SLICE);
    }
}

// round 3
// speedup vs baseline: 1.7939x; 1.0215x over previous
#include <cuda_runtime.h>

#define NB 8
#define PP 2304
#define QTOT (NB*PP)       // 18432
#define CIN 64
#define OUTC 384
#define NSTRIDE (OUTC*PP)
#define SLICE (64*PP)
#define NS 9               // split-K factor for visual attention

// Scratch (allocation-free rule: __device__ globals)
__device__ float g_q[NB*8*PP];
__device__ float g_k[NB*8*PP];
__device__ float g_v[NB*32*PP];
__device__ float g_pl[NS*QTOT];
__device__ float g_pv[NS*32*QTOT];
__device__ float g_x[QTOT*64];     // [p][n][c] mega-kernel input

typedef unsigned long long u64;

__device__ __forceinline__ u64 fma2(u64 a,u64 b,u64 c){u64 d;asm("fma.rn.f32x2 %0,%1,%2,%3;":"=l"(d):"l"(a),"l"(b),"l"(c));return d;}
__device__ __forceinline__ u64 add2(u64 a,u64 b){u64 d;asm("add.rn.f32x2 %0,%1,%2;":"=l"(d):"l"(a),"l"(b));return d;}
__device__ __forceinline__ u64 pack2(float lo,float hi){u64 d;asm("mov.b64 %0,{%1,%2};":"=l"(d):"f"(lo),"f"(hi));return d;}
__device__ __forceinline__ void unpack2(u64 v,float&lo,float&hi){asm("mov.b64 {%0,%1},%2;":"=f"(lo),"=f"(hi):"l"(v));}

// ---------------------------------------------------------------------------
// Stage-0 QKV: 64 -> 8(q) + 8(k) + 32(v,ReLU), packed f32x2 math.
// ---------------------------------------------------------------------------
__global__ __launch_bounds__(128) void qkv_kernel(
    const float* __restrict__ src,
    const float* __restrict__ qw, const float* __restrict__ qb,
    const float* __restrict__ kw, const float* __restrict__ kb,
    const float* __restrict__ vw, const float* __restrict__ vb)
{
    __shared__ alignas(16) u64 swt[CIN*24];   // [c][o2] packed output pairs
    __shared__ float sbs[48];
    const int tid = threadIdx.x;
    for (int i = tid; i < CIN*24; i += 128) {
        int c = i / 24, o2 = (i % 24) * 2, o1 = o2 + 1;
        float w0 = (o2 < 8) ? qw[o2*CIN+c] : (o2 < 16 ? kw[(o2-8)*CIN+c] : vw[(o2-16)*CIN+c]);
        float w1 = (o1 < 8) ? qw[o1*CIN+c] : (o1 < 16 ? kw[(o1-8)*CIN+c] : vw[(o1-16)*CIN+c]);
        swt[i] = pack2(w0, w1);
    }
    if (tid < 48) sbs[tid] = (tid<8)?qb[tid]:(tid<16?kb[tid-8]:vb[tid-16]);
    __syncthreads();

    const int gid = blockIdx.x*128 + tid;
    const int n = gid / PP, p = gid % PP;
    u64 acc[24];
    #pragma unroll
    for (int t=0;t<24;t++) acc[t] = pack2(sbs[2*t], sbs[2*t+1]);
    const float* xb = src + (long)n*CIN*PP + p;
    for (int c=0;c<CIN;c++) {
        float xv = xb[c*PP];
        u64 x2 = pack2(xv,xv);
        const ulonglong2* w2 = (const ulonglong2*)(swt + c*24);
        #pragma unroll
        for (int t=0;t<12;t++) { ulonglong2 w = w2[t];
            acc[2*t]   = fma2(x2, w.x, acc[2*t]);
            acc[2*t+1] = fma2(x2, w.y, acc[2*t+1]); }
    }
    float o[48];
    #pragma unroll
    for (int t=0;t<24;t++) unpack2(acc[t], o[2*t], o[2*t+1]);
    #pragma unroll
    for (int i=0;i<8;i++)  g_q[(n*8+i)*PP+p] = o[i];
    #pragma unroll
    for (int i=0;i<8;i++)  g_k[(n*8+i)*PP+p] = o[8+i];
    #pragma unroll
    for (int i=0;i<32;i++) g_v[(n*32+i)*PP+p] = fmaxf(o[16+i], 0.f);
}

// ---------------------------------------------------------------------------
// Visual attention, split-K: 48 query-tiles (384 q each, 3 q/thread) x 9 splits.
// One-pass softmax (logits O(1); shift-invariant); partials to g_pl/g_pv.
// ---------------------------------------------------------------------------
__global__ __launch_bounds__(128) void vis_attn_split(void)
{
    __shared__ alignas(16) u64 ksu[4*128];    // [c2][j]
    __shared__ alignas(16) u64 vsu[16*128];   // [c2][j]
    const int tid = threadIdx.x;
    const int tile = blockIdx.x / NS, split = blockIdx.x % NS;
    const int n = tile / 6, tw = tile % 6;
    const int qp = tw*384 + tid;
    const float* qb_ = g_q + n*8*PP;
    const float* kb_ = g_k + n*8*PP;
    const float* vb_ = g_v + n*32*PP;

    u64 qr[3][4];
    #pragma unroll
    for (int i=0;i<3;i++)
        #pragma unroll
        for (int r=0;r<4;r++)
            qr[i][r] = pack2(qb_[(2*r)*PP + qp + i*128], qb_[(2*r+1)*PP + qp + i*128]);

    float l[3] = {0.f, 0.f, 0.f};
    u64 vacc[3][16];
    #pragma unroll
    for (int i=0;i<3;i++)
        #pragma unroll
        for (int t=0;t<16;t++) vacc[i][t] = 0ULL;

    const u64 z = 0ULL;
    for (int ch = split*2; ch < split*2 + 2; ch++) {
        __syncthreads();
        const int base = ch*128 + tid;
        #pragma unroll
        for (int r=0;r<4;r++)  ksu[r*128+tid] = pack2(kb_[(2*r)*PP+base], kb_[(2*r+1)*PP+base]);
        #pragma unroll
        for (int t=0;t<16;t++) vsu[t*128+tid] = pack2(vb_[(2*t)*PP+base], vb_[(2*t+1)*PP+base]);
        __syncthreads();
        #pragma unroll 2
        for (int j=0;j<128;j++) {
            u64 k0 = ksu[j], k1 = ksu[128+j], k2 = ksu[256+j], k3 = ksu[384+j];
            float pr[3];
            #pragma unroll
            for (int i=0;i<3;i++) {
                u64 d = add2(fma2(qr[i][0],k0,fma2(qr[i][1],k1,z)),
                             fma2(qr[i][2],k2,fma2(qr[i][3],k3,z)));
                float lo,hi; unpack2(d,lo,hi);
                pr[i] = __expf(lo + hi);
                l[i] += pr[i];
            }
            u64 p0 = pack2(pr[0],pr[0]), p1 = pack2(pr[1],pr[1]), p2 = pack2(pr[2],pr[2]);
            #pragma unroll
            for (int t=0;t<16;t++) {
                u64 vr = vsu[t*128+j];
                vacc[0][t] = fma2(p0, vr, vacc[0][t]);
                vacc[1][t] = fma2(p1, vr, vacc[1][t]);
                vacc[2][t] = fma2(p2, vr, vacc[2][t]);
            }
        }
    }
    #pragma unroll
    for (int i=0;i<3;i++) {
        int q = n*PP + qp + i*128;
        g_pl[split*QTOT + q] = l[i];
        #pragma unroll
        for (int t=0;t<16;t++) {
            float lo,hi; unpack2(vacc[i][t], lo, hi);
            g_pv[(split*32 + 2*t  )*QTOT + q] = lo;
            g_pv[(split*32 + 2*t+1)*QTOT + q] = hi;
        }
    }
}

// ---------------------------------------------------------------------------
// Combine split-K partials + out-conv(32->32) + concat write to slice 0,
// plus write [oc, v] into g_x[p][n][c] for the mega temporal kernel.
// ---------------------------------------------------------------------------
__global__ __launch_bounds__(128) void combine_kernel(
    const float* __restrict__ cw, const float* __restrict__ cb,
    float* __restrict__ out)
{
    __shared__ alignas(16) u64 cwt[32*16];    // [c][o2]
    __shared__ alignas(16) float cbs[32];
    const int tid = threadIdx.x;
    for (int i = tid; i < 32*16; i += 128) {
        int c = i/16, t = i%16;
        cwt[i] = pack2(cw[(2*t)*32+c], cw[(2*t+1)*32+c]);
    }
    if (tid < 32) cbs[tid] = cb[tid];
    __syncthreads();

    const int gid = blockIdx.x*128 + tid;
    const int n = gid/PP, p = gid%PP;

    float l = 0.f;
    #pragma unroll
    for (int sp=0; sp<NS; sp++) l += g_pl[sp*QTOT + gid];
    float va[32];
    #pragma unroll
    for (int c=0;c<32;c++) va[c] = 0.f;
    for (int sp=0; sp<NS; sp++) {
        #pragma unroll
        for (int c=0;c<32;c++) va[c] += g_pv[(sp*32+c)*QTOT + gid];
    }
    float inv = 1.f / l;
    #pragma unroll
    for (int c=0;c<32;c++) va[c] *= inv;

    u64 acc[16];
    #pragma unroll
    for (int t=0;t<16;t++) acc[t] = pack2(cbs[2*t], cbs[2*t+1]);
    #pragma unroll
    for (int c=0;c<32;c++) {
        u64 x2 = pack2(va[c], va[c]);
        const ulonglong2* w2 = (const ulonglong2*)(cwt + c*16);
        #pragma unroll
        for (int t=0;t<8;t++){ ulonglong2 w = w2[t];
            acc[2*t] = fma2(x2,w.x,acc[2*t]); acc[2*t+1] = fma2(x2,w.y,acc[2*t+1]); }
    }
    float buf[64];
    #pragma unroll
    for (int t=0;t<16;t++) unpack2(acc[t], buf[2*t], buf[2*t+1]);
    #pragma unroll
    for (int c=0;c<32;c++) buf[32+c] = g_v[(n*32+c)*PP+p];

    float* ob = out + (long)n*NSTRIDE + p;   // slice 0
    #pragma unroll
    for (int o=0;o<32;o++) ob[o*PP] = buf[o];
    #pragma unroll
    for (int c=0;c<32;c++) ob[(32+c)*PP] = buf[32+c];

    float4* xp = (float4*)(g_x + ((long)p*8 + n)*64);
    #pragma unroll
    for (int t=0;t<16;t++) xp[t] = make_float4(buf[4*t],buf[4*t+1],buf[4*t+2],buf[4*t+3]);
}

// ---------------------------------------------------------------------------
// MEGA temporal kernel: all 5 heads in one launch.
// Lane mapping: n = tid&7 (batch frame), position = blockIdx*16 + tid>>3.
// precede() = __shfl_up within width-8 groups. Everything in registers;
// per-head weights reloaded into smem (coalesced) each iteration.
// ---------------------------------------------------------------------------
__global__ __launch_bounds__(128,1) void mega_temporal(
    const float* __restrict__ tq_w, const float* __restrict__ tq_b,
    const float* __restrict__ tk_w, const float* __restrict__ tk_b,
    const float* __restrict__ tv_w, const float* __restrict__ tv_b,
    const float* __restrict__ tc_w, const float* __restrict__ tc_b,
    float* __restrict__ out)
{
    __shared__ alignas(16) float swt[64*52];   // qkv weights [c][o], row pad 52 (16B-aligned rows)
    __shared__ alignas(16) float cwt[32*36];   // conv weights [c][o], row pad 36
    __shared__ alignas(16) float sbs[48];
    __shared__ alignas(16) float cbs[32];

    const int tid = threadIdx.x;
    const int n = tid & 7;
    const int pp = blockIdx.x*16 + (tid>>3);

    float x[64];
    {
        const float4* xp = (const float4*)(g_x + ((long)pp*8 + n)*64);
        #pragma unroll
        for (int t=0;t<16;t++){ float4 v4 = xp[t]; x[4*t]=v4.x; x[4*t+1]=v4.y; x[4*t+2]=v4.z; x[4*t+3]=v4.w; }
    }

    for (int h=0; h<5; h++) {
        __syncthreads();   // previous head done with smem weights
        for (int i=tid; i<48*64; i+=128) {   // coalesced over c (i&63)
            int o = i>>6, c = i&63;
            float w = (o<8)  ? tq_w[h*512  + o*64 + c]
                    : (o<16) ? tk_w[h*512  + (o-8)*64 + c]
                             : tv_w[h*2048 + (o-16)*64 + c];
            swt[c*52 + o] = w;
        }
        for (int i=tid; i<32*32; i+=128) {
            int o = i>>5, c = i&31;
            cwt[c*36 + o] = tc_w[h*1024 + o*32 + c];
        }
        if (tid < 48) sbs[tid] = (tid<8)? tq_b[h*8+tid] : (tid<16? tk_b[h*8+tid-8] : tv_b[h*32+tid-16]);
        if (tid < 32) cbs[tid] = tc_b[h*32+tid];
        __syncthreads();

        // ---- QKV: 64 -> 48, fully in registers, weights broadcast from smem
        u64 qa[24];
        {
            const u64* bp = (const u64*)sbs;
            #pragma unroll
            for (int t=0;t<24;t++) qa[t] = bp[t];
        }
        #pragma unroll
        for (int c=0;c<64;c++) {
            u64 x2 = pack2(x[c],x[c]);
            const u64* wr = (const u64*)(swt + c*52);
            #pragma unroll
            for (int t=0;t<24;t++) qa[t] = fma2(x2, wr[t], qa[t]);
        }
        float o48[48];
        #pragma unroll
        for (int t=0;t<24;t++) unpack2(qa[t], o48[2*t], o48[2*t+1]);
        float v[32];
        #pragma unroll
        for (int c=0;c<32;c++) v[c] = fmaxf(o48[16+c], 0.f);

        // ---- temporal softmax via width-8 shuffles
        float l2 = 0.f, l1 = 0.f, l0 = 0.f;
        #pragma unroll
        for (int c=0;c<8;c++) {
            float kc = o48[8+c];
            float k1 = __shfl_up_sync(0xffffffffu, kc, 1, 8);
            float k2 = __shfl_up_sync(0xffffffffu, kc, 2, 8);
            l2 += o48[c]*kc;
            l1 += o48[c]*k1;
            l0 += o48[c]*k2;
        }
        // zero-padded frames: logit exactly 0, still in the softmax
        if (n < 1) l1 = 0.f;
        if (n < 2) l0 = 0.f;
        float m  = fmaxf(l0, fmaxf(l1, l2));
        float e0 = __expf(l0-m), e1 = __expf(l1-m), e2 = __expf(l2-m);
        float inv = 1.f/(e0+e1+e2);
        float a0 = e0*inv, a1 = e1*inv, a2 = e2*inv;
        if (n < 1) a1 = 0.f;   // padded v is the zero tensor
        if (n < 2) a0 = 0.f;

        float av[32];
        #pragma unroll
        for (int c=0;c<32;c++) {
            float v1 = __shfl_up_sync(0xffffffffu, v[c], 1, 8);
            float v2 = __shfl_up_sync(0xffffffffu, v[c], 2, 8);
            av[c] = a2*v[c] + a1*v1 + a0*v2;
        }

        // ---- out-conv 32 -> 32
        u64 ca[16];
        {
            const u64* bp = (const u64*)cbs;
            #pragma unroll
            for (int t=0;t<16;t++) ca[t] = bp[t];
        }
        #pragma unroll
        for (int c=0;c<32;c++) {
            u64 x2 = pack2(av[c],av[c]);
            const u64* wr = (const u64*)(cwt + c*36);
            #pragma unroll
            for (int t=0;t<16;t++) ca[t] = fma2(x2, wr[t], ca[t]);
        }
        float oc[32];
        #pragma unroll
        for (int t=0;t<16;t++) unpack2(ca[t], oc[2*t], oc[2*t+1]);

        // ---- concat write to output slice h+1
        float* ob = out + (long)n*NSTRIDE + (long)(h+1)*SLICE + pp;
        #pragma unroll
        for (int c=0;c<32;c++) ob[c*PP] = oc[c];
        #pragma unroll
        for (int c=0;c<32;c++) ob[(32+c)*PP] = v[c];

        // ---- next head input
        #pragma unroll
        for (int c=0;c<32;c++) { x[c] = oc[c]; x[32+c] = v[c]; }
    }
}

// ---------------------------------------------------------------------------
extern "C" void kernel_launch(void* const* d_in, const int* in_sizes, int n_in,
                              void* d_out, int out_size)
{
    const float* x    = (const float*)d_in[0];
    const float* vq_w = (const float*)d_in[1];
    const float* vq_b = (const float*)d_in[2];
    const float* vk_w = (const float*)d_in[3];
    const float* vk_b = (const float*)d_in[4];
    const float* vv_w = (const float*)d_in[5];
    const float* vv_b = (const float*)d_in[6];
    const float* vc_w = (const float*)d_in[7];
    const float* vc_b = (const float*)d_in[8];
    const float* tq_w = (const float*)d_in[9];
    const float* tq_b = (const float*)d_in[10];
    const float* tk_w = (const float*)d_in[11];
    const float* tk_b = (const float*)d_in[12];
    const float* tv_w = (const float*)d_in[13];
    const float* tv_b = (const float*)d_in[14];
    const float* tc_w = (const float*)d_in[15];
    const float* tc_b = (const float*)d_in[16];
    float* out = (float*)d_out;

    qkv_kernel<<<144,128>>>(x, vq_w, vq_b, vk_w, vk_b, vv_w, vv_b);
    vis_attn_split<<<48*NS,128>>>();
    combine_kernel<<<144,128>>>(vc_w, vc_b, out);
    mega_temporal<<<144,128>>>(tq_w, tq_b, tk_w, tk_b, tv_w, tv_b, tc_w, tc_b, out);
}